// round 17
// baseline (speedup 1.0000x reference)
#include <cuda_runtime.h>
#include <cuda_fp16.h>
#include <math.h>
#include <stdint.h>

// Problem constants
#define TOK   4096   // B*L = 2*2048
#define DIMK  1024
#define HQ    16
#define HKV   4
#define HD    64
#define LSEQ  2048

// Scratch (static device globals — allocation-free)
__device__ float  g_q  [TOK * HQ  * HD];  // fp32 (normed * 1/8) for attention
__device__ float  g_k  [TOK * HKV * HD];  // fp32 (normed)
__device__ float  g_v  [TOK * HKV * HD];  // fp32
__device__ __half g_aoh[TOK * HQ * HD];   // attention out (fp16, oproj A operand)

// fp16 operands for the GEMMs
__device__ __half g_xh [TOK * DIMK];
__device__ __half g_wqh[HQ  * HD * DIMK];
__device__ __half g_wkh[HKV * HD * DIMK];
__device__ __half g_wvh[HKV * HD * DIMK];
__device__ __half g_woh[DIMK * HQ * HD];

// ---------------------------------------------------------------------------
// helpers
// ---------------------------------------------------------------------------
__device__ __forceinline__ uint32_t smem_u32(const void* p) {
    uint32_t a;
    asm("{ .reg .u64 t; cvta.to.shared.u64 t, %1; cvt.u32.u64 %0, t; }" : "=r"(a) : "l"(p));
    return a;
}

__device__ __forceinline__ void cp16(uint32_t dst, const void* src) {
    asm volatile("cp.async.cg.shared.global [%0], [%1], 16;" :: "r"(dst), "l"(src));
}
__device__ __forceinline__ void cp_commit() {
    asm volatile("cp.async.commit_group;" ::: "memory");
}
template <int N>
__device__ __forceinline__ void cp_wait() {
    asm volatile("cp.async.wait_group %0;" :: "n"(N) : "memory");
}

__device__ __forceinline__ void ldm_x4(unsigned& r0, unsigned& r1, unsigned& r2, unsigned& r3,
                                       uint32_t addr) {
    asm volatile("ldmatrix.sync.aligned.m8n8.x4.shared.b16 {%0,%1,%2,%3}, [%4];"
                 : "=r"(r0), "=r"(r1), "=r"(r2), "=r"(r3) : "r"(addr));
}

__device__ __forceinline__ void mma_f16(float& c0, float& c1, float& c2, float& c3,
                                        unsigned a0, unsigned a1, unsigned a2, unsigned a3,
                                        unsigned b0, unsigned b1)
{
    asm volatile(
        "mma.sync.aligned.m16n8k16.row.col.f32.f16.f16.f32 "
        "{%0,%1,%2,%3}, {%4,%5,%6,%7}, {%8,%9}, {%0,%1,%2,%3};"
        : "+f"(c0), "+f"(c1), "+f"(c2), "+f"(c3)
        : "r"(a0), "r"(a1), "r"(a2), "r"(a3), "r"(b0), "r"(b1));
}

__device__ __forceinline__ unsigned h2bits(float a, float b) {
    __half2 h = __floats2half2_rn(a, b);
    return *reinterpret_cast<unsigned*>(&h);
}

// ---------------------------------------------------------------------------
// Conversion prepass: fp32 -> fp16. Blocks: x 2048, wq 512, wk 128, wv 128,
// wo 512 (total 3328); each block 2048 elems (256 thr x 8).
// ---------------------------------------------------------------------------
__global__ void conv_kernel(const float* __restrict__ x,  const float* __restrict__ wq,
                            const float* __restrict__ wk, const float* __restrict__ wv,
                            const float* __restrict__ wo)
{
    const int b = blockIdx.x;
    const float* src;
    __half* dst;
    int base;
    if      (b < 2048) { src = x;  dst = g_xh;  base = b; }
    else if (b < 2560) { src = wq; dst = g_wqh; base = b - 2048; }
    else if (b < 2688) { src = wk; dst = g_wkh; base = b - 2560; }
    else if (b < 2816) { src = wv; dst = g_wvh; base = b - 2688; }
    else               { src = wo; dst = g_woh; base = b - 2816; }
    const size_t off = (size_t)base * 2048 + threadIdx.x * 8;
    float4 v0 = *(const float4*)(src + off);
    float4 v1 = *(const float4*)(src + off + 4);
    uint4 o;
    o.x = h2bits(v0.x, v0.y);
    o.y = h2bits(v0.z, v0.w);
    o.z = h2bits(v1.x, v1.y);
    o.w = h2bits(v1.z, v1.w);
    *(uint4*)(dst + off) = o;
}

// ---------------------------------------------------------------------------
// 128(M) x 64(N) tile fp16 GEMM, C[m,n] = sum_k A[m,k]*B[n,k] (both [rows][k],
// k contiguous, stride DIMK). BK=64 halves, 3-stage cp.async ring (24KB/stage,
// 72KB total -> 3 CTAs/SM). 256 threads, 8 warps, warp tile 16x64 via
// m16n8k16 + ldmatrix. Smem row = 128B = 8 x 16B chunks; phys = ch ^ (row&7).
// Fused per-head RMSNorm epilogue (tile = exactly one 64-dim head).
// ---------------------------------------------------------------------------
#define STG_A       16384              // A: 128 rows x 128B
#define STG_B       8192               // B:  64 rows x 128B
#define STAGE_BYTES (STG_A + STG_B)    // 24576
#define NSTAGE 3
#define DSMEM_SZ (NSTAGE * STAGE_BYTES)  // 73728
#define NSLAB (DIMK / 64)              // 16

__device__ __forceinline__ void gemm_128x64(const __half* __restrict__ Ag,
                                            const __half* __restrict__ Bg,
                                            float*        __restrict__ Cg,
                                            int ldc,
                                            const float* __restrict__ nw,
                                            float outScale)
{
    extern __shared__ char shraw[];
    const uint32_t sbase = smem_u32(shraw);

    const int tid    = threadIdx.x;
    const int lane   = tid & 31;
    const int wid    = tid >> 5;
    const int warp_m = wid * 16;
    const int g      = lane >> 2;
    const int tig    = lane & 3;

    float acc[8][4];
#pragma unroll
    for (int nt = 0; nt < 8; nt++)
#pragma unroll
        for (int c = 0; c < 4; c++) acc[nt][c] = 0.0f;

    // ---- A staging: thread -> row = tid>>1, 4 chunks of 16B (half = tid&1)
    const int arow = tid >> 1;
    const int hsel = tid & 1;
    const __half* Ap = Ag + (size_t)arow * DIMK + hsel * 32;
    uint32_t dstA[4];
#pragma unroll
    for (int i = 0; i < 4; i++) {
        const int ch = hsel * 4 + i;
        dstA[i] = arow * 128 + ((ch ^ (arow & 7)) << 4);
    }
    // ---- B staging: thread -> row = tid>>2, 2 chunks (quarter = tid&3)
    const int brow = tid >> 2;
    const int qsel = tid & 3;
    const __half* Bp = Bg + (size_t)brow * DIMK + qsel * 16;
    uint32_t dstB[2];
#pragma unroll
    for (int i = 0; i < 2; i++) {
        const int ch = qsel * 2 + i;
        dstB[i] = brow * 128 + ((ch ^ (brow & 7)) << 4);
    }

#define ISSUE_SLAB(s)                                                       \
    do {                                                                    \
        const uint32_t stb = sbase + ((s) % NSTAGE) * STAGE_BYTES;          \
        const __half* a_ = Ap + (s) * 64;                                   \
        const __half* b_ = Bp + (s) * 64;                                   \
        _Pragma("unroll")                                                   \
        for (int i_ = 0; i_ < 4; i_++) cp16(stb + dstA[i_], a_ + i_ * 8);   \
        _Pragma("unroll")                                                   \
        for (int i_ = 0; i_ < 2; i_++) cp16(stb + STG_A + dstB[i_], b_ + i_ * 8); \
        cp_commit();                                                        \
    } while (0)

    // ---- fragment addressing (ldmatrix), identical scheme to R16 ----------
    // A: lanes 0..15 -> rows warp_m..+15; lanes 16..31 -> same rows, k+8 chunk
    const int rA   = warp_m + (lane & 15);
    const uint32_t rowA = rA * 128;
    const int r7A  = rA & 7;
    const int cgA  = lane >> 4;
    // B (per ntp): rows ntp*16 + ((lane>>3)&1)*8 + (lane&7); lanes 16..31 k+8
    uint32_t rowB[4];
    int r7B[4];
#pragma unroll
    for (int ntp = 0; ntp < 4; ntp++) {
        const int r = ntp * 16 + ((lane >> 3) & 1) * 8 + (lane & 7);
        rowB[ntp] = r * 128;
        r7B[ntp]  = r & 7;
    }
    const int cgB = lane >> 4;

    ISSUE_SLAB(0);
    ISSUE_SLAB(1);

    for (int s = 0; s < NSLAB; s++) {
        cp_wait<1>();
        __syncthreads();

        if (s + 2 < NSLAB) ISSUE_SLAB(s + 2);

        const uint32_t stA = sbase + (s % NSTAGE) * STAGE_BYTES;
        const uint32_t stB = stA + STG_A;

#pragma unroll
        for (int ks = 0; ks < 4; ks++) {
            const int kc = 2 * ks;
            unsigned a0, a1, a2, a3;
            const uint32_t ad = stA + rowA + (((kc + cgA) ^ r7A) << 4);
            ldm_x4(a0, a1, a2, a3, ad);
#pragma unroll
            for (int ntp = 0; ntp < 4; ntp++) {
                unsigned b0, b1, b2, b3;
                const uint32_t bd = stB + rowB[ntp] + (((kc + cgB) ^ r7B[ntp]) << 4);
                ldm_x4(b0, b1, b2, b3, bd);
                const int n0 = 2 * ntp, n1 = 2 * ntp + 1;
                mma_f16(acc[n0][0], acc[n0][1], acc[n0][2], acc[n0][3],
                        a0, a1, a2, a3, b0, b2);
                mma_f16(acc[n1][0], acc[n1][1], acc[n1][2], acc[n1][3],
                        a0, a1, a2, a3, b1, b3);
            }
        }
        __syncthreads();
    }
#undef ISSUE_SLAB

    // ---------------- Epilogue ----------------
    // Thread owns rows (warp_m+g) and (warp_m+8+g), cols nt*8 + tig*2 (+1).
    if (nw == nullptr) {
#pragma unroll
        for (int nt = 0; nt < 8; nt++) {
            const int c = nt * 8 + tig * 2;
            *(float2*)(Cg + (size_t)(warp_m + g) * ldc + c)     = make_float2(acc[nt][0], acc[nt][1]);
            *(float2*)(Cg + (size_t)(warp_m + 8 + g) * ldc + c) = make_float2(acc[nt][2], acc[nt][3]);
        }
    } else {
        // Fused per-head RMSNorm: the tile's 64 cols = one head; row ss via
        // per-thread partial (16 cols) + quad shuffle.
        float w[16];
#pragma unroll
        for (int nt = 0; nt < 8; nt++) {
            float2 ww = *(const float2*)(nw + nt * 8 + tig * 2);
            w[nt * 2]     = ww.x;
            w[nt * 2 + 1] = ww.y;
        }
        float s0 = 0.f, s1 = 0.f;
#pragma unroll
        for (int nt = 0; nt < 8; nt++) {
            s0 += acc[nt][0] * acc[nt][0] + acc[nt][1] * acc[nt][1];
            s1 += acc[nt][2] * acc[nt][2] + acc[nt][3] * acc[nt][3];
        }
        s0 += __shfl_xor_sync(0xffffffffu, s0, 1);
        s0 += __shfl_xor_sync(0xffffffffu, s0, 2);
        s1 += __shfl_xor_sync(0xffffffffu, s1, 1);
        s1 += __shfl_xor_sync(0xffffffffu, s1, 2);
        const float n0 = rsqrtf(s0 * (1.0f / 64.0f) + 0.01f) * outScale;
        const float n1 = rsqrtf(s1 * (1.0f / 64.0f) + 0.01f) * outScale;
#pragma unroll
        for (int nt = 0; nt < 8; nt++) {
            const int c = nt * 8 + tig * 2;
            *(float2*)(Cg + (size_t)(warp_m + g) * ldc + c) =
                make_float2(acc[nt][0] * n0 * w[nt * 2], acc[nt][1] * n0 * w[nt * 2 + 1]);
            *(float2*)(Cg + (size_t)(warp_m + 8 + g) * ldc + c) =
                make_float2(acc[nt][2] * n1 * w[nt * 2], acc[nt][3] * n1 * w[nt * 2 + 1]);
        }
    }
}

// ---------------------------------------------------------------------------
// Fused QKV projection + per-head RMSNorm epilogue: grid (24, 32).
// nb 0..15 -> q head nb (norm, *1/8), 16..19 -> k (norm), 20..23 -> v.
// ---------------------------------------------------------------------------
__global__ void __launch_bounds__(256, 3)
qkv_kernel(const float* __restrict__ qnw, const float* __restrict__ knw)
{
    const int nb = blockIdx.x;
    const int mb = blockIdx.y;
    const __half* Bg;
    float* Cg;
    int ldc;
    const float* nw;
    float sc;
    if (nb < 16) {
        Bg  = g_wqh + (size_t)nb * 64 * DIMK;
        Cg  = g_q + (size_t)mb * 128 * 1024 + nb * 64;
        ldc = 1024; nw = qnw; sc = 0.125f;     // fold softmax 1/sqrt(64)
    } else if (nb < 20) {
        int t = nb - 16;
        Bg  = g_wkh + (size_t)t * 64 * DIMK;
        Cg  = g_k + (size_t)mb * 128 * 256 + t * 64;
        ldc = 256; nw = knw; sc = 1.0f;
    } else {
        int t = nb - 20;
        Bg  = g_wvh + (size_t)t * 64 * DIMK;
        Cg  = g_v + (size_t)mb * 128 * 256 + t * 64;
        ldc = 256; nw = nullptr; sc = 1.0f;
    }
    gemm_128x64(g_xh + (size_t)mb * 128 * DIMK, Bg, Cg, ldc, nw, sc);
}

// ---------------------------------------------------------------------------
// Output projection: out = g_aoh @ wo^T, grid (16, 32).
// ---------------------------------------------------------------------------
__global__ void __launch_bounds__(256, 3)
oproj_kernel(float* __restrict__ out)
{
    gemm_128x64(g_aoh + (size_t)blockIdx.y * 128 * 1024,
                g_woh + (size_t)blockIdx.x * 64 * DIMK,
                out   + (size_t)blockIdx.y * 128 * 1024 + blockIdx.x * 64,
                1024, nullptr, 1.0f);
}

// ---------------------------------------------------------------------------
// Sliding-window ALiBi attention (R12 layout). fp32 math; stores fp16 output.
// Warp = 4 queries of one (b,h) as four 8-lane groups; lane owns 8 dims.
// ---------------------------------------------------------------------------
__global__ void attn_kernel()
{
    const int gw   = (blockIdx.x * blockDim.x + threadIdx.x) >> 5;
    const int lane = threadIdx.x & 31;
    const int gid  = lane >> 3;
    const int sub  = lane & 7;
    const int b   = gw >> 13;
    const int h   = (gw >> 9) & 15;
    const int i0  = (gw & 511) << 2;
    const int i   = i0 + gid;
    const int kvh = h & 3;

    const float slope = exp2f(-0.5f * (float)(h + 1));

    const float* qp = g_q + ((size_t)(b * LSEQ + i) * 1024) + h * 64 + sub * 8;
    const float4 q0 = *(const float4*)qp;
    const float4 q1 = *(const float4*)(qp + 4);

    const float* kp = g_k + (size_t)b * LSEQ * 256 + kvh * 64 + sub * 8;
    const float* vp = g_v + (size_t)b * LSEQ * 256 + kvh * 64 + sub * 8;

    float m = -1e30f, l = 0.0f;
    float o0 = 0.f, o1 = 0.f, o2 = 0.f, o3 = 0.f;
    float o4 = 0.f, o5 = 0.f, o6 = 0.f, o7 = 0.f;

    int jlo = i0 - 16; if (jlo < 0) jlo = 0;
    for (int j = jlo; j <= i0 + 3; j++) {
        const float* kr = kp + (size_t)j * 256;
        const float* vr = vp + (size_t)j * 256;
        const float4 k0 = *(const float4*)kr;
        const float4 k1 = *(const float4*)(kr + 4);
        const float4 v0 = *(const float4*)vr;
        const float4 v1 = *(const float4*)(vr + 4);

        float s = q0.x * k0.x + q0.y * k0.y + q0.z * k0.z + q0.w * k0.w
                + q1.x * k1.x + q1.y * k1.y + q1.z * k1.z + q1.w * k1.w;
        s += __shfl_xor_sync(0xffffffffu, s, 1);
        s += __shfl_xor_sync(0xffffffffu, s, 2);
        s += __shfl_xor_sync(0xffffffffu, s, 4);

        const bool active = (j <= i) && (j >= i - 16);
        if (active) {
            s += slope * (float)(j - i);
            const float mn = fmaxf(m, s);
            const float c  = __expf(m - mn);
            const float p  = __expf(s - mn);
            l  = l * c + p;
            o0 = o0 * c + p * v0.x;  o1 = o1 * c + p * v0.y;
            o2 = o2 * c + p * v0.z;  o3 = o3 * c + p * v0.w;
            o4 = o4 * c + p * v1.x;  o5 = o5 * c + p * v1.y;
            o6 = o6 * c + p * v1.z;  o7 = o7 * c + p * v1.w;
            m = mn;
        }
    }

    const float inv = 1.0f / l;
    __half* op = g_aoh + ((size_t)(b * LSEQ + i) * 1024) + h * 64 + sub * 8;
    uint4 o;
    o.x = h2bits(o0 * inv, o1 * inv);
    o.y = h2bits(o2 * inv, o3 * inv);
    o.z = h2bits(o4 * inv, o5 * inv);
    o.w = h2bits(o6 * inv, o7 * inv);
    *(uint4*)op = o;
}

// ---------------------------------------------------------------------------
// Launch sequence (graph-capturable: kernel launches only, default stream)
// Inputs: 0=x, 1=wq, 2=wk, 3=wv, 4=wo, 5=q_norm_w, 6=k_norm_w
// ---------------------------------------------------------------------------
extern "C" void kernel_launch(void* const* d_in, const int* in_sizes, int n_in,
                              void* d_out, int out_size)
{
    const float* x   = (const float*)d_in[0];
    const float* wq  = (const float*)d_in[1];
    const float* wk  = (const float*)d_in[2];
    const float* wv  = (const float*)d_in[3];
    const float* wo  = (const float*)d_in[4];
    const float* qnw = (const float*)d_in[5];
    const float* knw = (const float*)d_in[6];
    float* out = (float*)d_out;

    cudaFuncSetAttribute((const void*)qkv_kernel,
                         cudaFuncAttributeMaxDynamicSharedMemorySize, DSMEM_SZ);
    cudaFuncSetAttribute((const void*)oproj_kernel,
                         cudaFuncAttributeMaxDynamicSharedMemorySize, DSMEM_SZ);

    // 0) Convert operands to fp16
    conv_kernel<<<3328, 256>>>(x, wq, wk, wv, wo);

    // 1) QKV projection + fused RMSNorm epilogue (fp16 tensor cores)
    qkv_kernel<<<dim3(24, 32), 256, DSMEM_SZ>>>(qnw, knw);

    // 2) Sliding-window ALiBi attention (writes fp16 output)
    attn_kernel<<<2048, 256>>>();

    // 3) Output projection (fp16 tensor cores)
    oproj_kernel<<<dim3(16, 32), 256, DSMEM_SZ>>>(out);
}